// round 1
// baseline (speedup 1.0000x reference)
#include <cuda_runtime.h>
#include <cstddef>

#define N_    128
#define CIN   8
#define HIN   128
#define WIN   128
#define COUT  64
#define OH    126
#define OW    126
#define G_    16
#define CPG   4
#define OPH   31
#define OPW   31
#define WPAD  128          // padded scratch row (floats) for aligned float4
#define TH    8            // output rows per chunk
#define TROWS (TH + 2)     // input rows per tile
#define SQ4   33           // float4 per smem row (132 floats: 128 + pad)

// Scratch: conv output, padded rows. 128*64*126*128 floats = 528 MB.
__device__ float g_y[(size_t)N_ * COUT * OH * WPAD];
__device__ float g_sum[N_ * G_];
__device__ float g_sqs[N_ * G_];
__device__ float g_mean[N_ * G_];
__device__ float g_rsig[N_ * G_];

// ---------------------------------------------------------------------------
// Kernel 1: conv(3x3, 8->4 channels of this group) + bias, write scratch,
// block-local deterministic reduction of sum / sumsq for GroupNorm.
// One block per (group, n). 256 threads.
// Thread layout per chunk: row = tid>>5 (0..7), wg = tid&31, w0 = wg*4.
// Each thread produces 4 output channels x 4 adjacent w positions.
// ---------------------------------------------------------------------------
__global__ __launch_bounds__(256) void conv_stats_kernel(
    const float* __restrict__ x,
    const float* __restrict__ cw,
    const float* __restrict__ cb)
{
    __shared__ float4 s_in[CIN][TROWS][SQ4];   // 42240 B
    __shared__ float4 s_w[CIN][3][CPG];        // 1536 B: (w0,w1,w2,0)
    __shared__ float  s_bias[CPG];
    __shared__ float  s_red[512];

    const int g   = blockIdx.x;
    const int n   = blockIdx.y;
    const int tid = threadIdx.x;

    // Load weights (96 float4) + bias
    if (tid < 96) {
        int oc = tid & 3;
        int t  = tid >> 2;          // 0..23 = ic*3 + kh
        int ic = t / 3, kh = t - 3 * ic;
        const float* wp = cw + ((((size_t)g * CPG + oc) * CIN + ic) * 3 + kh) * 3;
        s_w[ic][kh][oc] = make_float4(wp[0], wp[1], wp[2], 0.f);
    }
    if (tid < CPG) s_bias[tid] = cb[g * CPG + tid];

    const int row = tid >> 5;
    const int wg  = tid & 31;
    const int w0  = wg * 4;

    const float* xn = x + (size_t)n * CIN * HIN * WIN;
    float* yg = g_y + (size_t)(n * COUT + g * CPG) * OH * WPAD;

    float tsum = 0.f, tsq = 0.f;

    for (int chunk = 0; chunk < 16; ++chunk) {
        const int r0 = chunk * TH;
        __syncthreads();   // protect smem reuse across chunks

        // Load input tile: 8 ic x 10 rows x 32 float4 = 2560 float4
        for (int idx = tid; idx < CIN * TROWS * 32; idx += 256) {
            int ic  = idx / (TROWS * 32);
            int rem = idx - ic * (TROWS * 32);
            int r   = rem >> 5;
            int c4  = rem & 31;
            int ih  = r0 + r;
            float4 v = make_float4(0.f, 0.f, 0.f, 0.f);
            if (ih < HIN)
                v = *(const float4*)(xn + ((size_t)ic * HIN + ih) * WIN + c4 * 4);
            s_in[ic][r][c4] = v;
        }
        if (tid < CIN * TROWS) {
            int ic = tid / TROWS, r = tid - ic * TROWS;
            s_in[ic][r][32] = make_float4(0.f, 0.f, 0.f, 0.f);
        }
        __syncthreads();

        const int orow = r0 + row;
        if (orow < OH) {
            float acc[CPG][4];
            #pragma unroll
            for (int oc = 0; oc < CPG; ++oc) {
                acc[oc][0] = 0.f; acc[oc][1] = 0.f;
                acc[oc][2] = 0.f; acc[oc][3] = 0.f;
            }

            #pragma unroll 2
            for (int ic = 0; ic < CIN; ++ic) {
                #pragma unroll
                for (int kh = 0; kh < 3; ++kh) {
                    float4 A = s_in[ic][row + kh][wg];
                    float4 B = s_in[ic][row + kh][wg + 1];
                    float i0 = A.x, i1 = A.y, i2 = A.z, i3 = A.w, i4 = B.x, i5 = B.y;
                    #pragma unroll
                    for (int oc = 0; oc < CPG; ++oc) {
                        float4 wv = s_w[ic][kh][oc];
                        acc[oc][0] = fmaf(i2, wv.z, fmaf(i1, wv.y, fmaf(i0, wv.x, acc[oc][0])));
                        acc[oc][1] = fmaf(i3, wv.z, fmaf(i2, wv.y, fmaf(i1, wv.x, acc[oc][1])));
                        acc[oc][2] = fmaf(i4, wv.z, fmaf(i3, wv.y, fmaf(i2, wv.x, acc[oc][2])));
                        acc[oc][3] = fmaf(i5, wv.z, fmaf(i4, wv.y, fmaf(i3, wv.x, acc[oc][3])));
                    }
                }
            }

            const bool full = (w0 + 3 < OW);   // only wg==31 is partial (2 valid)
            #pragma unroll
            for (int oc = 0; oc < CPG; ++oc) {
                float b  = s_bias[oc];
                float v0 = acc[oc][0] + b;
                float v1 = acc[oc][1] + b;
                float v2 = acc[oc][2] + b;
                float v3 = acc[oc][3] + b;
                // cols >= 126 are never read back (pool uses cols 0..123)
                *(float4*)(yg + ((size_t)oc * OH + orow) * WPAD + w0) =
                    make_float4(v0, v1, v2, v3);
                tsum += v0 + v1;
                tsq  = fmaf(v0, v0, tsq); tsq = fmaf(v1, v1, tsq);
                if (full) {
                    tsum += v2 + v3;
                    tsq  = fmaf(v2, v2, tsq); tsq = fmaf(v3, v3, tsq);
                }
            }
        }
    }

    // Deterministic block reduction (256 -> 1)
    __syncthreads();
    s_red[tid]       = tsum;
    s_red[256 + tid] = tsq;
    __syncthreads();
    for (int s = 128; s > 0; s >>= 1) {
        if (tid < s) {
            s_red[tid]       += s_red[tid + s];
            s_red[256 + tid] += s_red[256 + tid + s];
        }
        __syncthreads();
    }
    if (tid == 0) {
        g_sum[n * G_ + g] = s_red[0];
        g_sqs[n * G_ + g] = s_red[256];
    }
}

// ---------------------------------------------------------------------------
// Kernel 2: finalize stats -> mean, rsig per (n, group)
// ---------------------------------------------------------------------------
__global__ void stats_finalize_kernel()
{
    int i = blockIdx.x * blockDim.x + threadIdx.x;
    if (i < N_ * G_) {
        const float inv_cnt = 1.f / (float)(CPG * OH * OW);
        float mean = g_sum[i] * inv_cnt;
        float var  = g_sqs[i] * inv_cnt - mean * mean;
        g_mean[i] = mean;
        g_rsig[i] = rsqrtf(var + 1e-5f);
    }
}

// ---------------------------------------------------------------------------
// Kernel 3: GN affine + per-channel scale folded into (a,b), 4x4 maxpool, clamp
// ---------------------------------------------------------------------------
__global__ __launch_bounds__(256) void pool_kernel(
    const float* __restrict__ gnw,
    const float* __restrict__ gnb,
    const float* __restrict__ scale,
    float* __restrict__ out)
{
    const int total = N_ * COUT * OPH * OPW;
    int idx = blockIdx.x * 256 + threadIdx.x;
    if (idx >= total) return;

    int j = idx % OPW;
    int t = idx / OPW;
    int i = t % OPH;  t /= OPH;
    int c = t % COUT;
    int n = t / COUT;

    int gi = n * G_ + (c >> 2);
    float mean = g_mean[gi];
    float rsig = g_rsig[gi];
    float sw   = scale[c];
    float gw   = gnw[c];
    float a = rsig * gw * sw;
    float b = (gnb[c] - mean * rsig * gw) * sw;

    const float* base = g_y + (((size_t)(n * COUT + c)) * OH + (size_t)i * 4) * WPAD + j * 4;
    float m = -3.4e38f;
    #pragma unroll
    for (int r = 0; r < 4; ++r) {
        float4 v = *(const float4*)(base + (size_t)r * WPAD);
        float m0 = fmaxf(fmaf(v.x, a, b), fmaf(v.y, a, b));
        float m1 = fmaxf(fmaf(v.z, a, b), fmaf(v.w, a, b));
        m = fmaxf(m, fmaxf(m0, m1));
    }
    out[idx] = fminf(fmaxf(m, 0.f), 1.f);
}

// ---------------------------------------------------------------------------
extern "C" void kernel_launch(void* const* d_in, const int* in_sizes, int n_in,
                              void* d_out, int out_size)
{
    const float* x     = (const float*)d_in[0];
    const float* cw    = (const float*)d_in[1];
    const float* cb    = (const float*)d_in[2];
    const float* gnw   = (const float*)d_in[3];
    const float* gnb   = (const float*)d_in[4];
    const float* scale = (const float*)d_in[5];
    float* out = (float*)d_out;

    dim3 grid1(G_, N_);
    conv_stats_kernel<<<grid1, 256>>>(x, cw, cb);

    stats_finalize_kernel<<<(N_ * G_ + 255) / 256, 256>>>();

    const int total = N_ * COUT * OPH * OPW;
    pool_kernel<<<(total + 255) / 256, 256>>>(gnw, gnb, scale, out);
}